// round 1
// baseline (speedup 1.0000x reference)
#include <cuda_runtime.h>
#include <math.h>

#define NEGV (-1e30f)

// B=8, S=512, L=32, M=64
#define B_ 8
#define S_ 512
#define L_ 32
#define M_ 64

// scratch[b][e][cur][jm1] = segment_score[b][e-jm1][e][cur]   (segment length j = jm1+1, start = e-jm1)
__device__ float g_scratch[B_ * S_ * L_ * M_];   // 32 MB

__device__ __forceinline__ float warp_max(float v) {
#pragma unroll
    for (int o = 16; o; o >>= 1) v = fmaxf(v, __shfl_xor_sync(0xffffffffu, v, o));
    return v;
}
__device__ __forceinline__ float warp_sum(float v) {
#pragma unroll
    for (int o = 16; o; o >>= 1) v += __shfl_xor_sync(0xffffffffu, v, o);
    return v;
}

// -------- pre-pass: gather the band (last M starts per end) into contiguous layout --------
__global__ void transpose_kernel(const float* __restrict__ seg) {
    // one block per (b, e); 256 threads
    int be = blockIdx.x;
    int b = be >> 9;          // / 512
    int e = be & (S_ - 1);
    __shared__ float tile[L_][M_ + 1];   // [cur][jm1], padded

    int tid = threadIdx.x;
    // phase 1: read rows seg[b][e-jm1][e][0..31] (contiguous 128B each)
    for (int idx = tid; idx < M_ * L_; idx += 256) {
        int jm1 = idx >> 5;       // 0..63
        int c   = idx & 31;
        float v = 0.0f;
        int s = e - jm1;
        if (s >= 0) {
            v = seg[(((size_t)b * S_ + s) * S_ + e) * L_ + c];
        }
        tile[c][jm1] = v;
    }
    __syncthreads();
    // phase 2: write scratch[b][e][cur][0..63] contiguously
    float* out = &g_scratch[((size_t)(b * S_ + e)) * (L_ * M_)];
    for (int idx = tid; idx < L_ * M_; idx += 256) {
        int c   = idx >> 6;
        int jm1 = idx & 63;
        out[idx] = tile[c][jm1];
    }
}

// -------- sequential recurrence: one CTA per batch, 32 warps (warp = cur label) --------
__global__ __launch_bounds__(1024, 1) void crf_kernel(const float* __restrict__ trans,
                                                      float* __restrict__ out) {
    __shared__ float s_trans[L_ * 33];     // [prev][cur] padded
    __shared__ float s_diag[L_];
    __shared__ float s_alpha[2][L_];       // double buffered
    __shared__ float s_beta[M_ * 33];      // ring: frame p -> s_beta[(p&63)*33 + cur]

    const int b    = blockIdx.x;
    const int tid  = threadIdx.x;
    const int cur  = tid >> 5;
    const int lane = tid & 31;

    // load transitions (row-major [prev][cur])
    {
        int p = tid >> 5, c = tid & 31;
        float t = trans[tid];
        s_trans[p * 33 + c] = t;
        if (p == c) s_diag[p] = t;
    }
    // ring init to NEG (acts as -inf guard for frames < 0)
    for (int i = tid; i < M_ * 33; i += 1024) s_beta[i] = NEGV;
    // alpha[frame 0][cur] = seg(0,0,cur) = scratch[b][0][cur][0]
    if (tid < L_) s_alpha[0][tid] = g_scratch[((size_t)(b * S_)) * (L_ * M_) + tid * M_];
    __syncthreads();

    const float diag = s_diag[cur];
    const float* seg_base = &g_scratch[((size_t)(b * S_)) * (L_ * M_)];

    // prefetch row for f = 1
    float sega, segb;
    {
        const float* row = seg_base + (size_t)(1 * L_ + cur) * M_;
        sega = row[lane];
        segb = row[lane + 32];
    }

    const int j1 = lane + 1;     // segment lengths handled by this lane
    const int j2 = lane + 33;
    const float fj1 = (float)j1, fj2 = (float)j2;
    const float d1 = diag * (float)(j1 - 1);
    const float d2 = diag * (float)(j2 - 1);

    for (int f = 1; f < S_; ++f) {
        const int rbuf = (f - 1) & 1;
        const int wbuf = f & 1;

        // ---- beta for frame f-1: LSE_prev( alpha[f-1][prev] + T[prev][cur] ) ----
        float v = s_alpha[rbuf][lane] + s_trans[lane * 33 + cur];
        float bm = warp_max(v);
        float bs = warp_sum(__expf(v - bm));
        float beta = bm + __logf(bs);               // all lanes hold it
        if (lane == 0) s_beta[((f - 1) & 63) * 33 + cur] = beta;

        // ---- prefetch next seg row ----
        float nsega = 0.0f, nsegb = 0.0f;
        if (f + 1 < S_) {
            const float* nrow = seg_base + (size_t)((f + 1) * L_ + cur) * M_;
            nsega = nrow[lane];
            nsegb = nrow[lane + 32];
        }

        // ---- alpha[f][cur] = LSE_j( beta[f-j][cur] + seg(f-j+1,f,cur)*j + diag*(j-1) ) (+ init) ----
        float bt1 = (lane == 0) ? beta : s_beta[((f - j1) & 63) * 33 + cur];
        float bt2 = s_beta[((f - j2) & 63) * 33 + cur];
        float t1 = bt1 + sega * fj1 + d1;
        float t2 = bt2 + segb * fj2 + d2;

        // initial segment [0, f]: valid only when f < M. seg value is scratch[b][f][cur][f].
        float t3 = NEGV;
        if (f < M_) {
            float sf = (f < 32) ? __shfl_sync(0xffffffffu, sega, f)
                                : __shfl_sync(0xffffffffu, segb, f - 32);
            if (lane == 0) t3 = sf * (float)(f + 1) + diag * (float)f;
        }

        float lm = fmaxf(fmaxf(t1, t2), t3);
        float am = warp_max(lm);
        float ls = __expf(t1 - am) + __expf(t2 - am) + __expf(t3 - am);
        float as = warp_sum(ls);
        float alpha_new = am + __logf(as);

        if (lane == 0) s_alpha[wbuf][cur] = alpha_new;
        __syncthreads();   // alpha visible for next step's beta (double-buffered: no WAR sync)

        sega = nsega;
        segb = nsegb;
    }

    // ---- log_z = LSE_cur alpha[S-1][cur] ----
    if (cur == 0) {
        float a = s_alpha[(S_ - 1) & 1][lane];
        float m = warp_max(a);
        float s = warp_sum(__expf(a - m));
        if (lane == 0) out[b] = m + __logf(s);
    }
}

extern "C" void kernel_launch(void* const* d_in, const int* in_sizes, int n_in,
                              void* d_out, int out_size) {
    const float* seg   = (const float*)d_in[0];
    const float* trans = (const float*)d_in[1];
    // defensive: pick by size (transitions has 1024 elements)
    if (n_in >= 2 && in_sizes[0] == L_ * L_) {
        trans = (const float*)d_in[0];
        seg   = (const float*)d_in[1];
    }
    float* out = (float*)d_out;

    transpose_kernel<<<B_ * S_, 256>>>(seg);
    crf_kernel<<<B_, 1024>>>(trans, out);
}